// round 5
// baseline (speedup 1.0000x reference)
#include <cuda_runtime.h>
#include <cuda_bf16.h>
#include <math.h>
#include <stdint.h>

#define BB  2
#define SS  2048
#define HH  4096
#define NH  32
#define NKV 8
#define HD  128
#define MR  (BB * SS)      // 4096 rows
#define QD  (NH * HD)      // 4096
#define KVD (NKV * HD)     // 1024

// ---------------- scratch (device globals; no runtime allocation) ----------
__device__ float g_q[MR * QD];
__device__ float g_k[MR * KVD];
__device__ float g_v[MR * KVD];
__device__ float g_att[MR * QD];

__device__ __nv_bfloat16 g_hs_h[MR * HH];
__device__ __nv_bfloat16 g_hs_l[MR * HH];
__device__ __nv_bfloat16 g_wqT_h[QD * HH];
__device__ __nv_bfloat16 g_wqT_l[QD * HH];
__device__ __nv_bfloat16 g_wkT_h[KVD * HH];
__device__ __nv_bfloat16 g_wkT_l[KVD * HH];
__device__ __nv_bfloat16 g_wvT_h[KVD * HH];
__device__ __nv_bfloat16 g_wvT_l[KVD * HH];
__device__ __nv_bfloat16 g_woT_h[HH * QD];
__device__ __nv_bfloat16 g_woT_l[HH * QD];
__device__ __nv_bfloat16 g_att_h[MR * QD];
__device__ __nv_bfloat16 g_att_l[MR * QD];

// attention operands (post-RoPE, hi/lo split)
__device__ __nv_bfloat16 g_qr_h[MR * QD];
__device__ __nv_bfloat16 g_qr_l[MR * QD];
__device__ __nv_bfloat16 g_kr_h[MR * KVD];
__device__ __nv_bfloat16 g_kr_l[MR * KVD];
__device__ __nv_bfloat16 g_vr_h[MR * KVD];
__device__ __nv_bfloat16 g_vr_l[MR * KVD];

// ---------------- PTX helpers ----------------------------------------------
__device__ __forceinline__ uint32_t smem_u32(const void* p) {
    uint32_t a;
    asm("{ .reg .u64 t; cvta.to.shared.u64 t, %1; cvt.u32.u64 %0, t; }"
        : "=r"(a) : "l"(p));
    return a;
}
__device__ __forceinline__ void cpasync16(uint32_t dst, const void* src) {
    asm volatile("cp.async.cg.shared.global [%0], [%1], 16;"
                 :: "r"(dst), "l"(src));
}
#define CP_COMMIT() asm volatile("cp.async.commit_group;" ::: "memory")
#define CP_WAIT0()  asm volatile("cp.async.wait_group 0;" ::: "memory")

#define LDSM4(r0, r1, r2, r3, addr) \
    asm volatile("ldmatrix.sync.aligned.m8n8.x4.shared.b16 {%0,%1,%2,%3}, [%4];" \
                 : "=r"(r0), "=r"(r1), "=r"(r2), "=r"(r3) : "r"(addr))

#define LDSM4T(r0, r1, r2, r3, addr) \
    asm volatile("ldmatrix.sync.aligned.m8n8.x4.trans.shared.b16 {%0,%1,%2,%3}, [%4];" \
                 : "=r"(r0), "=r"(r1), "=r"(r2), "=r"(r3) : "r"(addr))

#define MMA_BF16(c, a, b) \
    asm volatile("mma.sync.aligned.m16n8k16.row.col.f32.bf16.bf16.f32 " \
                 "{%0,%1,%2,%3}, {%4,%5,%6,%7}, {%8,%9}, {%0,%1,%2,%3};" \
                 : "+f"((c)[0]), "+f"((c)[1]), "+f"((c)[2]), "+f"((c)[3]) \
                 : "r"((a)[0]), "r"((a)[1]), "r"((a)[2]), "r"((a)[3]), \
                   "r"((b)[0]), "r"((b)[1]))

__device__ __forceinline__ void split2(float x, float y, uint32_t& h, uint32_t& l) {
    __nv_bfloat162 hb = __floats2bfloat162_rn(x, y);
    float2 hf = __bfloat1622float2(hb);
    __nv_bfloat162 lb = __floats2bfloat162_rn(x - hf.x, y - hf.y);
    h = *reinterpret_cast<uint32_t*>(&hb);
    l = *reinterpret_cast<uint32_t*>(&lb);
}

// ---------------------------------------------------------------------------
// fp32 -> bf16 hi/lo split (elementwise, vectorized by 4)
// ---------------------------------------------------------------------------
__global__ void split_kernel(const float* __restrict__ src,
                             __nv_bfloat16* __restrict__ hi,
                             __nv_bfloat16* __restrict__ lo, int n4) {
    int i = blockIdx.x * blockDim.x + threadIdx.x;
    if (i >= n4) return;
    float4 s = ((const float4*)src)[i];
    __nv_bfloat162 h01 = __floats2bfloat162_rn(s.x, s.y);
    __nv_bfloat162 h23 = __floats2bfloat162_rn(s.z, s.w);
    float2 f01 = __bfloat1622float2(h01);
    float2 f23 = __bfloat1622float2(h23);
    __nv_bfloat162 l01 = __floats2bfloat162_rn(s.x - f01.x, s.y - f01.y);
    __nv_bfloat162 l23 = __floats2bfloat162_rn(s.z - f23.x, s.w - f23.y);
    ((__nv_bfloat162*)hi)[2 * i]     = h01;
    ((__nv_bfloat162*)hi)[2 * i + 1] = h23;
    ((__nv_bfloat162*)lo)[2 * i]     = l01;
    ((__nv_bfloat162*)lo)[2 * i + 1] = l23;
}

// ---------------------------------------------------------------------------
// Weight transpose + split: W[K,N] fp32 -> hiT/loT [N,K] bf16
// ---------------------------------------------------------------------------
__global__ void split_transpose(const float* __restrict__ W,
                                __nv_bfloat16* __restrict__ hiT,
                                __nv_bfloat16* __restrict__ loT, int K, int N) {
    __shared__ float t[32][33];
    int n0 = blockIdx.x * 32, k0 = blockIdx.y * 32;
    int tx = threadIdx.x, ty = threadIdx.y;
#pragma unroll
    for (int i = 0; i < 32; i += 8)
        t[ty + i][tx] = W[(size_t)(k0 + ty + i) * N + n0 + tx];
    __syncthreads();
#pragma unroll
    for (int i = 0; i < 32; i += 8) {
        float v = t[tx][ty + i];
        __nv_bfloat16 h = __float2bfloat16_rn(v);
        __nv_bfloat16 l = __float2bfloat16_rn(v - __bfloat162float(h));
        size_t o = (size_t)(n0 + ty + i) * K + k0 + tx;
        hiT[o] = h;
        loT[o] = l;
    }
}

// ---------------------------------------------------------------------------
// mma.sync bf16x3 GEMM: C[M,N] = A[M,K] @ BT[N,K]^T  (fp32-accurate)
// ---------------------------------------------------------------------------
#define TILE_B   10240
#define STAGE_B  (4 * TILE_B)
#define GEMM_SMEM (2 * STAGE_B)

__global__ __launch_bounds__(256, 1)
void mma_gemm(const __nv_bfloat16* __restrict__ Ahi,
              const __nv_bfloat16* __restrict__ Alo,
              const __nv_bfloat16* __restrict__ Bhi,
              const __nv_bfloat16* __restrict__ Blo,
              float* __restrict__ C, int Nd, int Kd) {
    extern __shared__ char smem[];
    const uint32_t sb = smem_u32(smem);
    const int tid = threadIdx.x;
    const int wid = tid >> 5, lid = tid & 31;
    const int wm = wid >> 2, wn = wid & 3;
    const int bn = blockIdx.x * 128, bm = blockIdx.y * 128;

    float c[4][4][4];
#pragma unroll
    for (int i = 0; i < 4; i++)
#pragma unroll
        for (int j = 0; j < 4; j++)
#pragma unroll
            for (int q = 0; q < 4; q++) c[i][j][q] = 0.f;

    const int rowA = lid & 15;
    const int khA  = (lid >> 4) << 3;
    const int nB   = ((lid >> 4) << 3) + (lid & 7);
    const int khB  = ((lid >> 3) & 1) << 3;

#define LOAD_STAGE(s, k0)                                                     \
    do {                                                                      \
        _Pragma("unroll")                                                     \
        for (int li = 0; li < 2; li++) {                                      \
            int id  = li * 256 + tid;                                         \
            int row = id >> 2, seg = id & 3;                                  \
            uint32_t so = sb + (s) * STAGE_B + row * 80 + seg * 16;           \
            size_t ga = (size_t)(bm + row) * Kd + (k0) + seg * 8;             \
            size_t gb = (size_t)(bn + row) * Kd + (k0) + seg * 8;             \
            cpasync16(so,              Ahi + ga);                             \
            cpasync16(so + TILE_B,     Alo + ga);                             \
            cpasync16(so + 2 * TILE_B, Bhi + gb);                             \
            cpasync16(so + 3 * TILE_B, Blo + gb);                             \
        }                                                                     \
        CP_COMMIT();                                                          \
    } while (0)

    const int nk = Kd >> 5;
    LOAD_STAGE(0, 0);

    for (int kt = 0; kt < nk; kt++) {
        CP_WAIT0();
        __syncthreads();
        if (kt + 1 < nk) LOAD_STAGE((kt + 1) & 1, (kt + 1) << 5);

        const uint32_t abase = sb + (kt & 1) * STAGE_B;
        const uint32_t bbase = abase + 2 * TILE_B;
#pragma unroll
        for (int kk = 0; kk < 32; kk += 16) {
            uint32_t bh[4][2], bl[4][2];
#pragma unroll
            for (int j2 = 0; j2 < 2; j2++) {
                uint32_t ba = bbase + (wn * 32 + j2 * 16 + nB) * 80 +
                              (kk + khB) * 2;
                LDSM4(bh[j2 * 2][0], bh[j2 * 2][1],
                      bh[j2 * 2 + 1][0], bh[j2 * 2 + 1][1], ba);
                LDSM4(bl[j2 * 2][0], bl[j2 * 2][1],
                      bl[j2 * 2 + 1][0], bl[j2 * 2 + 1][1], ba + TILE_B);
            }
#pragma unroll
            for (int i = 0; i < 4; i++) {
                uint32_t aa = abase + (wm * 64 + i * 16 + rowA) * 80 +
                              (kk + khA) * 2;
                uint32_t ah[4], al[4];
                LDSM4(ah[0], ah[1], ah[2], ah[3], aa);
                LDSM4(al[0], al[1], al[2], al[3], aa + TILE_B);
#pragma unroll
                for (int j = 0; j < 4; j++) {
                    MMA_BF16(c[i][j], ah, bh[j]);
                    MMA_BF16(c[i][j], ah, bl[j]);
                    MMA_BF16(c[i][j], al, bh[j]);
                }
            }
        }
        __syncthreads();
    }
#undef LOAD_STAGE

    const int g = lid >> 2, t4 = lid & 3;
#pragma unroll
    for (int i = 0; i < 4; i++) {
        int r0 = bm + wm * 64 + i * 16 + g;
#pragma unroll
        for (int j = 0; j < 4; j++) {
            int col = bn + wn * 32 + j * 8 + t4 * 2;
            *(float2*)&C[(size_t)r0 * Nd + col] =
                make_float2(c[i][j][0], c[i][j][1]);
            *(float2*)&C[(size_t)(r0 + 8) * Nd + col] =
                make_float2(c[i][j][2], c[i][j][3]);
        }
    }
}

// ---------------------------------------------------------------------------
// Fused RoPE + bf16 hi/lo split: reads fp32, writes rotated hi/lo bf16.
// pos = row % SS (position_ids == tile(arange(S)))
// ---------------------------------------------------------------------------
__global__ void rope_split(const float* __restrict__ buf,
                           __nv_bfloat16* __restrict__ oh,
                           __nv_bfloat16* __restrict__ ol, int nheads) {
    int idx = blockIdx.x * blockDim.x + threadIdx.x;
    int total = MR * nheads * 64;
    if (idx >= total) return;
    int i    = idx & 63;
    int head = (idx >> 6) % nheads;
    int row  = idx / (nheads << 6);

    float p    = (float)(row % SS);
    float invf = expf(-(float)i * 0.14391156831212787f);
    float ang  = p * invf;
    float c, s;
    sincosf(ang, &s, &c);

    size_t base = (size_t)row * (nheads * HD) + head * HD + i;
    float x0 = buf[base];
    float x1 = buf[base + 64];
    float y0 = x0 * c - x1 * s;
    float y1 = x1 * c + x0 * s;

    __nv_bfloat16 h0 = __float2bfloat16_rn(y0);
    __nv_bfloat16 h1 = __float2bfloat16_rn(y1);
    oh[base]      = h0;
    oh[base + 64] = h1;
    ol[base]      = __float2bfloat16_rn(y0 - __bfloat162float(h0));
    ol[base + 64] = __float2bfloat16_rn(y1 - __bfloat162float(h1));
}

// ---------------------------------------------------------------------------
// Tensor-core causal flash attention, bf16x3 both GEMMs, fp32 softmax.
// CTA: 64 q-rows x 1 head. 128 threads = 4 warps, 16 rows each.
// Smem tiles at 272B pitch (conflict-free ldmatrix / ldmatrix.trans).
// ---------------------------------------------------------------------------
#define APITCH 272                       // bytes per 128-bf16 row (136 bf16)
#define ATILE  (64 * APITCH)             // 17408 B
#define ATTN_SMEM (6 * ATILE)            // Qh Ql Kh Kl Vh Vl

__global__ __launch_bounds__(128)
void attn_mma(const __nv_bfloat16* __restrict__ Qh, const __nv_bfloat16* __restrict__ Ql,
              const __nv_bfloat16* __restrict__ Kh, const __nv_bfloat16* __restrict__ Kl,
              const __nv_bfloat16* __restrict__ Vh, const __nv_bfloat16* __restrict__ Vl,
              float* __restrict__ O) {
    extern __shared__ char smem[];
    const uint32_t sb = smem_u32(smem);
    const int tid = threadIdx.x;
    const int wid = tid >> 5, lid = tid & 31;
    const int g = lid >> 2, t4 = lid & 3;
    const int qb = blockIdx.x, h = blockIdx.y, b = blockIdx.z;
    const int kvh = h >> 2;
    const int q0 = qb * 64;

    const uint32_t sQh = sb,             sQl = sb + ATILE;
    const uint32_t sKh = sb + 2 * ATILE, sKl = sb + 3 * ATILE;
    const uint32_t sVh = sb + 4 * ATILE, sVl = sb + 5 * ATILE;

    // Q tile load (once)
#pragma unroll
    for (int t = 0; t < 8; t++) {
        int id = t * 128 + tid;
        int row = id >> 4, seg = id & 15;
        uint32_t so = row * APITCH + seg * 16;
        size_t gq = (size_t)(b * SS + q0 + row) * QD + h * HD + seg * 8;
        cpasync16(sQh + so, Qh + gq);
        cpasync16(sQl + so, Ql + gq);
    }
    CP_COMMIT();

    float o[16][4];
#pragma unroll
    for (int n = 0; n < 16; n++)
#pragma unroll
        for (int q = 0; q < 4; q++) o[n][q] = 0.f;
    float m[2] = {-1e30f, -1e30f}, l[2] = {0.f, 0.f};

    // ldmatrix lane addressing
    const int rowA = lid & 15, khA = (lid >> 4) << 3;                 // A (Q)
    const int nB = ((lid >> 4) << 3) + (lid & 7);                     // B (K)
    const int khB = ((lid >> 3) & 1) << 3;
    const int kV = (((lid >> 3) & 1) << 3) + (lid & 7);               // B (V, trans)
    const int nVo = (lid >> 4) << 3;

    const float scale = 0.08838834764831845f;  // 1/sqrt(128)

    for (int kb = 0; kb <= qb; kb++) {
        const int k0t = kb * 64;
        __syncthreads();
#pragma unroll
        for (int t = 0; t < 8; t++) {
            int id = t * 128 + tid;
            int row = id >> 4, seg = id & 15;
            uint32_t so = row * APITCH + seg * 16;
            size_t gk = (size_t)(b * SS + k0t + row) * KVD + kvh * HD + seg * 8;
            cpasync16(sKh + so, Kh + gk);
            cpasync16(sKl + so, Kl + gk);
            cpasync16(sVh + so, Vh + gk);
            cpasync16(sVl + so, Vl + gk);
        }
        CP_COMMIT();
        CP_WAIT0();
        __syncthreads();

        // ---- S = Q K^T (bf16x3) ----
        float sc[8][4];
#pragma unroll
        for (int j = 0; j < 8; j++)
#pragma unroll
            for (int q = 0; q < 4; q++) sc[j][q] = 0.f;

#pragma unroll
        for (int kk = 0; kk < 8; kk++) {
            uint32_t qhf[4], qlf[4];
            uint32_t qa = sQh + (wid * 16 + rowA) * APITCH + (kk * 16 + khA) * 2;
            LDSM4(qhf[0], qhf[1], qhf[2], qhf[3], qa);
            LDSM4(qlf[0], qlf[1], qlf[2], qlf[3], qa + (sQl - sQh));
#pragma unroll
            for (int jp = 0; jp < 4; jp++) {
                uint32_t kh0[2], kh1[2], kl0[2], kl1[2];
                uint32_t ka = sKh + (jp * 16 + nB) * APITCH + (kk * 16 + khB) * 2;
                LDSM4(kh0[0], kh0[1], kh1[0], kh1[1], ka);
                LDSM4(kl0[0], kl0[1], kl1[0], kl1[1], ka + (sKl - sKh));
                MMA_BF16(sc[2 * jp],     qhf, kh0);
                MMA_BF16(sc[2 * jp],     qhf, kl0);
                MMA_BF16(sc[2 * jp],     qlf, kh0);
                MMA_BF16(sc[2 * jp + 1], qhf, kh1);
                MMA_BF16(sc[2 * jp + 1], qhf, kl1);
                MMA_BF16(sc[2 * jp + 1], qlf, kh1);
            }
        }

        // scale + causal mask (diagonal tile only)
#pragma unroll
        for (int j = 0; j < 8; j++)
#pragma unroll
            for (int q = 0; q < 4; q++) sc[j][q] *= scale;
        if (kb == qb) {
            int r0l = wid * 16 + g, r1l = r0l + 8;
#pragma unroll
            for (int j = 0; j < 8; j++) {
                int c0 = j * 8 + 2 * t4, c1 = c0 + 1;
                if (c0 > r0l) sc[j][0] = -1e30f;
                if (c1 > r0l) sc[j][1] = -1e30f;
                if (c0 > r1l) sc[j][2] = -1e30f;
                if (c1 > r1l) sc[j][3] = -1e30f;
            }
        }

        // ---- online softmax (rows g, g+8 of this warp's slab) ----
#pragma unroll
        for (int r = 0; r < 2; r++) {
            float mx = -1e30f;
#pragma unroll
            for (int j = 0; j < 8; j++)
                mx = fmaxf(mx, fmaxf(sc[j][2 * r], sc[j][2 * r + 1]));
            mx = fmaxf(mx, __shfl_xor_sync(0xffffffffu, mx, 1));
            mx = fmaxf(mx, __shfl_xor_sync(0xffffffffu, mx, 2));
            float mn = fmaxf(m[r], mx);
            float corr = __expf(m[r] - mn);
            float rs = 0.f;
#pragma unroll
            for (int j = 0; j < 8; j++) {
                float p0 = __expf(sc[j][2 * r] - mn);
                float p1 = __expf(sc[j][2 * r + 1] - mn);
                sc[j][2 * r] = p0;
                sc[j][2 * r + 1] = p1;
                rs += p0 + p1;
            }
            rs += __shfl_xor_sync(0xffffffffu, rs, 1);
            rs += __shfl_xor_sync(0xffffffffu, rs, 2);
            l[r] = l[r] * corr + rs;
            m[r] = mn;
#pragma unroll
            for (int n = 0; n < 16; n++) {
                o[n][2 * r] *= corr;
                o[n][2 * r + 1] *= corr;
            }
        }

        // ---- O += P V (bf16x3, P from registers) ----
#pragma unroll
        for (int j2 = 0; j2 < 4; j2++) {
            uint32_t ah[4], al[4];
            split2(sc[2 * j2][0],     sc[2 * j2][1],     ah[0], al[0]);
            split2(sc[2 * j2][2],     sc[2 * j2][3],     ah[1], al[1]);
            split2(sc[2 * j2 + 1][0], sc[2 * j2 + 1][1], ah[2], al[2]);
            split2(sc[2 * j2 + 1][2], sc[2 * j2 + 1][3], ah[3], al[3]);
#pragma unroll
            for (int np = 0; np < 8; np++) {
                uint32_t vh0[2], vh1[2], vl0[2], vl1[2];
                uint32_t va = sVh + (j2 * 16 + kV) * APITCH + (np * 16 + nVo) * 2;
                LDSM4T(vh0[0], vh0[1], vh1[0], vh1[1], va);
                LDSM4T(vl0[0], vl0[1], vl1[0], vl1[1], va + (sVl - sVh));
                MMA_BF16(o[2 * np],     ah, vh0);
                MMA_BF16(o[2 * np],     ah, vl0);
                MMA_BF16(o[2 * np],     al, vh0);
                MMA_BF16(o[2 * np + 1], ah, vh1);
                MMA_BF16(o[2 * np + 1], ah, vl1);
                MMA_BF16(o[2 * np + 1], al, vh1);
            }
        }
    }

    // ---- finalize & store ----
    float inv0 = 1.f / l[0], inv1 = 1.f / l[1];
    size_t r0g = (size_t)(b * SS + q0 + wid * 16 + g) * QD + h * HD;
    size_t r1g = r0g + 8 * QD;
#pragma unroll
    for (int n = 0; n < 16; n++) {
        int col = n * 8 + 2 * t4;
        *(float2*)&O[r0g + col] = make_float2(o[n][0] * inv0, o[n][1] * inv0);
        *(float2*)&O[r1g + col] = make_float2(o[n][2] * inv1, o[n][3] * inv1);
    }
}

// ---------------------------------------------------------------------------
extern "C" void kernel_launch(void* const* d_in, const int* in_sizes, int n_in,
                              void* d_out, int out_size) {
    const float* hs  = (const float*)d_in[0];
    const float* Wq  = (const float*)d_in[2];
    const float* Wk  = (const float*)d_in[3];
    const float* Wv  = (const float*)d_in[4];
    const float* Wo  = (const float*)d_in[5];
    float*       out = (float*)d_out;

    float *qb, *kb, *vb, *ab;
    cudaGetSymbolAddress((void**)&qb, g_q);
    cudaGetSymbolAddress((void**)&kb, g_k);
    cudaGetSymbolAddress((void**)&vb, g_v);
    cudaGetSymbolAddress((void**)&ab, g_att);

    __nv_bfloat16 *hsh, *hsl, *wqh, *wql, *wkh, *wkl, *wvh, *wvl, *woh, *wol, *ath, *atl;
    __nv_bfloat16 *qrh, *qrl, *krh, *krl, *vrh, *vrl;
    cudaGetSymbolAddress((void**)&hsh, g_hs_h);
    cudaGetSymbolAddress((void**)&hsl, g_hs_l);
    cudaGetSymbolAddress((void**)&wqh, g_wqT_h);
    cudaGetSymbolAddress((void**)&wql, g_wqT_l);
    cudaGetSymbolAddress((void**)&wkh, g_wkT_h);
    cudaGetSymbolAddress((void**)&wkl, g_wkT_l);
    cudaGetSymbolAddress((void**)&wvh, g_wvT_h);
    cudaGetSymbolAddress((void**)&wvl, g_wvT_l);
    cudaGetSymbolAddress((void**)&woh, g_woT_h);
    cudaGetSymbolAddress((void**)&wol, g_woT_l);
    cudaGetSymbolAddress((void**)&ath, g_att_h);
    cudaGetSymbolAddress((void**)&atl, g_att_l);
    cudaGetSymbolAddress((void**)&qrh, g_qr_h);
    cudaGetSymbolAddress((void**)&qrl, g_qr_l);
    cudaGetSymbolAddress((void**)&krh, g_kr_h);
    cudaGetSymbolAddress((void**)&krl, g_kr_l);
    cudaGetSymbolAddress((void**)&vrh, g_vr_h);
    cudaGetSymbolAddress((void**)&vrl, g_vr_l);

    cudaFuncSetAttribute(mma_gemm, cudaFuncAttributeMaxDynamicSharedMemorySize, GEMM_SMEM);
    cudaFuncSetAttribute(attn_mma, cudaFuncAttributeMaxDynamicSharedMemorySize, ATTN_SMEM);

    // split inputs to bf16 hi/lo
    split_kernel<<<(MR * HH / 4 + 255) / 256, 256>>>(hs, hsh, hsl, MR * HH / 4);
    split_transpose<<<dim3(QD / 32, HH / 32), dim3(32, 8)>>>(Wq, wqh, wql, HH, QD);
    split_transpose<<<dim3(KVD / 32, HH / 32), dim3(32, 8)>>>(Wk, wkh, wkl, HH, KVD);
    split_transpose<<<dim3(KVD / 32, HH / 32), dim3(32, 8)>>>(Wv, wvh, wvl, HH, KVD);
    split_transpose<<<dim3(HH / 32, QD / 32), dim3(32, 8)>>>(Wo, woh, wol, QD, HH);

    // QKV projections (tensor cores, bf16x3)
    mma_gemm<<<dim3(QD / 128, MR / 128), 256, GEMM_SMEM>>>(hsh, hsl, wqh, wql, qb, QD, HH);
    mma_gemm<<<dim3(KVD / 128, MR / 128), 256, GEMM_SMEM>>>(hsh, hsl, wkh, wkl, kb, KVD, HH);
    mma_gemm<<<dim3(KVD / 128, MR / 128), 256, GEMM_SMEM>>>(hsh, hsl, wvh, wvl, vb, KVD, HH);

    // RoPE fused with hi/lo split; V split
    rope_split<<<(MR * NH * 64 + 255) / 256, 256>>>(qb, qrh, qrl, NH);
    rope_split<<<(MR * NKV * 64 + 255) / 256, 256>>>(kb, krh, krl, NKV);
    split_kernel<<<(MR * KVD / 4 + 255) / 256, 256>>>(vb, vrh, vrl, MR * KVD / 4);

    // causal GQA attention (tensor cores, bf16x3)
    attn_mma<<<dim3(SS / 64, NH, BB), 128, ATTN_SMEM>>>(qrh, qrl, krh, krl, vrh, vrl, ab);

    // split attention output, then O projection (tensor cores)
    split_kernel<<<(MR * QD / 4 + 255) / 256, 256>>>(ab, ath, atl, MR * QD / 4);
    mma_gemm<<<dim3(HH / 128, MR / 128), 256, GEMM_SMEM>>>(ath, atl, woh, wol, out, HH, QD);
}